// round 1
// baseline (speedup 1.0000x reference)
#include <cuda_runtime.h>
#include <cstdint>
#include <math.h>

#define BN_EPS 1e-5f

// ---------------- packed weights / folded BN constants ----------------
__device__ uint32_t g_wky[6];      // per ky: bit (6*c+kx) = (conv_w[c,0,ky,kx] > 0)
__device__ float    g_cs[5];       // conv BN scale
__device__ float    g_csh[5];      // conv BN shift (conv_b folded in)
__device__ uint32_t g_fcw[10][5];  // per (j,c): bit p (0..24) = (fc_w[j, c*25+p] > 0)
__device__ float    g_fs[10];      // fc BN scale
__device__ float    g_fsh[10];     // fc BN shift (fc_b folded in)

__global__ void prep_kernel(
    const float* __restrict__ conv_w, const float* __restrict__ conv_b,
    const float* __restrict__ g2, const float* __restrict__ b2,
    const float* __restrict__ m2, const float* __restrict__ v2,
    const float* __restrict__ fc_w, const float* __restrict__ fc_b,
    const float* __restrict__ g1, const float* __restrict__ b1,
    const float* __restrict__ m1, const float* __restrict__ v1)
{
    int t = threadIdx.x;
    if (t < 6) {                       // ky = t : pack conv weight sign bits
        uint32_t w = 0;
        for (int c = 0; c < 5; c++)
            for (int kx = 0; kx < 6; kx++)
                if (conv_w[c * 36 + t * 6 + kx] > 0.f) w |= 1u << (6 * c + kx);
        g_wky[t] = w;
    }
    if (t >= 8 && t < 13) {            // c = t-8 : conv BN fold
        int c = t - 8;
        float s = g2[c] * rsqrtf(v2[c] + BN_EPS);
        g_cs[c]  = s;
        g_csh[c] = (conv_b[c] - m2[c]) * s + b2[c];
    }
    if (t >= 16 && t < 26) {           // j = t-16 : fc weight bits + BN fold
        int j = t - 16;
        for (int c = 0; c < 5; c++) {
            uint32_t w = 0;
            for (int p = 0; p < 25; p++)
                if (fc_w[j * 125 + c * 25 + p] > 0.f) w |= 1u << p;
            g_fcw[j][c] = w;
        }
        float s = g1[j] * rsqrtf(v1[j] + BN_EPS);
        g_fs[j]  = s;
        g_fsh[j] = (fc_b[j] - m1[j]) * s + b1[j];
    }
}

// byte code per pixel: bit0 = (x>0), bit1 = (x!=0)   (sign(0)=0 handling + padding-free)
__device__ __forceinline__ uint32_t binz(float f) {
    uint32_t u = __float_as_uint(f);
    uint32_t pos = ((int)u > 0) ? 1u : 0u;       // positive non-NaN floats are >0 as int
    uint32_t nz  = ((u << 1) != 0u) ? 2u : 0u;   // kills +0.0 and -0.0
    return pos | nz;
}

__global__ __launch_bounds__(256) void bnn_kernel(
    const float* __restrict__ x, float* __restrict__ out, int B)
{
    __shared__ uint32_t s_bytes[8][196];  // packed sign bytes (4 px / word)
    __shared__ uint32_t s_prow[8][28];    // per-row pos bits, pre-shifted <<2
    __shared__ uint32_t s_nrow[8][28];    // per-row nonzero bits, pre-shifted <<2

    const int warp = threadIdx.x >> 5;
    const int lane = threadIdx.x & 31;
    const int img  = blockIdx.x * 8 + warp;
    if (img >= B) return;                 // warp-uniform

    // ---- stage: coalesced float4 loads, binarize to byte codes ----
    const float4* xv = (const float4*)(x + (size_t)img * 784);
    #pragma unroll
    for (int k = 0; k < 7; k++) {
        int f = k * 32 + lane;
        if (k < 6 || f < 196) {
            float4 v = xv[f];
            uint32_t w = binz(v.x) | (binz(v.y) << 8) | (binz(v.z) << 16) | (binz(v.w) << 24);
            s_bytes[warp][f] = w;
        }
    }
    __syncwarp();

    // ---- build per-row bitmasks (28 bits, stored <<2 so window shift is 6*ox) ----
    if (lane < 28) {
        uint32_t pr = 0, nr = 0;
        #pragma unroll
        for (int t = 0; t < 7; t++) {
            uint32_t w  = s_bytes[warp][lane * 7 + t];
            uint32_t tp = (w & 0x01010101u) * 0x01020408u;        // bits 24..27 = b0..b3
            uint32_t tn = ((w >> 1) & 0x01010101u) * 0x01020408u;
            pr |= ((tp >> 24) & 0xFu) << (4 * t);
            nr |= ((tn >> 24) & 0xFu) << (4 * t);
        }
        s_prow[warp][lane] = pr << 2;
        s_nrow[warp][lane] = nr << 2;
    }
    __syncwarp();

    // ---- conv via XNOR-popcount: lane p<25 handles (oy,ox)=(p/5,p%5), all 5 channels ----
    const int p  = (lane < 25) ? lane : 0;
    const int oy = p / 5, ox = p % 5;
    const int sh = 6 * ox;                 // rows stored <<2, so col window = >> (6*ox)

    uint32_t d[5] = {0, 0, 0, 0, 0};
    int pmsum = 0;
    #pragma unroll
    for (int ky = 0; ky < 6; ky++) {
        int r = 6 * oy - 2 + ky;           // each input row maps to exactly one oy
        if (r >= 0) {                      // rows -2,-1 are padding (only for oy==0)
            uint32_t pr = s_prow[warp][r];
            uint32_t nr = s_nrow[warp][r];
            uint32_t xw = (pr >> sh) & 0x3Fu;   // pos bits in window (padding cols = 0)
            uint32_t mw = (nr >> sh) & 0x3Fu;   // valid (nonzero, in-bounds) bits
            pmsum += __popc(mw);
            uint32_t wk = g_wky[ky];
            d[0] += __popc(~(xw ^ (wk      )) & mw);
            d[1] += __popc(~(xw ^ (wk >> 6 )) & mw);
            d[2] += __popc(~(xw ^ (wk >> 12)) & mw);
            d[3] += __popc(~(xw ^ (wk >> 18)) & mw);
            d[4] += __popc(~(xw ^ (wk >> 24)) & mw);
        }
    }

    // ---- BN + hardtanh + sign -> ballot-pack 125 bits as 5 words of 25 bits ----
    const bool act = (lane < 25);
    uint32_t pb[5], nb[5];
    #pragma unroll
    for (int c = 0; c < 5; c++) {
        float y = (float)(2 * (int)d[c] - pmsum) * g_cs[c] + g_csh[c];
        pb[c] = __ballot_sync(0xFFFFFFFFu, act && (y > 0.f));
        nb[c] = __ballot_sync(0xFFFFFFFFu, act && (y < 0.f));
    }

    // ---- binary FC (10 outputs on lanes 0..9) ----
    uint32_t mm[5];
    int pmf = 0;
    #pragma unroll
    for (int c = 0; c < 5; c++) { mm[c] = pb[c] | nb[c]; pmf += __popc(mm[c]); }

    const int j = (lane < 10) ? lane : 0;
    int D = 0;
    #pragma unroll
    for (int c = 0; c < 5; c++)
        D += __popc(~(pb[c] ^ g_fcw[j][c]) & mm[c]);
    float z = (float)(2 * D - pmf) * g_fs[j] + g_fsh[j];

    // ---- log_softmax across 10 lanes (full-warp butterfly, identity padding) ----
    float zv = (lane < 10) ? z : -INFINITY;
    float m = zv;
    #pragma unroll
    for (int o = 16; o; o >>= 1) m = fmaxf(m, __shfl_xor_sync(0xFFFFFFFFu, m, o));
    float e = expf(zv - m);                       // lanes>=10: exp(-inf)=0
    float se = e;
    #pragma unroll
    for (int o = 16; o; o >>= 1) se += __shfl_xor_sync(0xFFFFFFFFu, se, o);

    if (lane < 10) out[(size_t)img * 10 + lane] = z - m - logf(se);
}

extern "C" void kernel_launch(void* const* d_in, const int* in_sizes, int n_in,
                              void* d_out, int out_size)
{
    const float* x = (const float*)d_in[0];
    prep_kernel<<<1, 32>>>(
        (const float*)d_in[1], (const float*)d_in[2],
        (const float*)d_in[3], (const float*)d_in[4],
        (const float*)d_in[5], (const float*)d_in[6],
        (const float*)d_in[7], (const float*)d_in[8],
        (const float*)d_in[9], (const float*)d_in[10],
        (const float*)d_in[11], (const float*)d_in[12]);

    int B = in_sizes[0] / 784;
    int blocks = (B + 7) / 8;
    bnn_kernel<<<blocks, 256>>>(x, (float*)d_out, B);
}

// round 3
// speedup vs baseline: 1.2445x; 1.2445x over previous
#include <cuda_runtime.h>
#include <cstdint>
#include <math.h>

#define BN_EPS 1e-5f

// ---------------- packed weights / folded constants ----------------
__device__ uint2  g_cw[5];           // per c: lo = bits (6*ky+kx) for ky<5, hi = bits kx for ky=5 ; bit=(w>0)
__device__ float4 g_bn2[5];          // (conv_b, bn2_mean, g2/sqrt(v2+eps), bn2_beta)
__device__ __align__(16) uint32_t g_fcw[10][8];  // [j][c] bit p = fc_w[j, 25c+p] > 0
__device__ float4 g_fcc[10];         // (fc_b, bn1_mean, g1/sqrt(v1+eps), bn1_beta)

__global__ void prep_kernel(
    const float* __restrict__ conv_w, const float* __restrict__ conv_b,
    const float* __restrict__ g2, const float* __restrict__ b2,
    const float* __restrict__ m2, const float* __restrict__ v2,
    const float* __restrict__ fc_w, const float* __restrict__ fc_b,
    const float* __restrict__ g1, const float* __restrict__ b1,
    const float* __restrict__ m1, const float* __restrict__ v1)
{
    int t = threadIdx.x;
    if (t < 50) {                              // fc weight bits: (j, c)
        int j = t / 5, c = t % 5;
        uint32_t wv = 0;
        for (int p = 0; p < 25; p++)
            if (fc_w[j * 125 + c * 25 + p] > 0.f) wv |= 1u << p;
        g_fcw[j][c] = wv;
    } else if (t < 55) {                       // conv weight bits: c
        int c = t - 50;
        uint32_t lo = 0, hi = 0;
        for (int ky = 0; ky < 6; ky++)
            for (int kx = 0; kx < 6; kx++) {
                uint32_t bit = (conv_w[c * 36 + ky * 6 + kx] > 0.f) ? 1u : 0u;
                if (ky < 5) lo |= bit << (6 * ky + kx);
                else        hi |= bit << kx;
            }
        g_cw[c] = make_uint2(lo, hi);
    } else if (t < 60) {                       // conv BN consts
        int c = t - 55;
        float s = g2[c] / sqrtf(v2[c] + BN_EPS);
        g_bn2[c] = make_float4(conv_b[c], m2[c], s, b2[c]);
    } else if (t < 70) {                       // fc BN consts
        int j = t - 60;
        float s = g1[j] / sqrtf(v1[j] + BN_EPS);
        g_fcc[j] = make_float4(fc_b[j], m1[j], s, b1[j]);
    }
}

__global__ __launch_bounds__(256) void bnn_kernel(
    const float* __restrict__ x, float* __restrict__ out, int B)
{
    __shared__ uint32_t s_stream[8][28];   // neg-bit stream (784 bits -> 25 words)
    __shared__ uint32_t s_prow[8][32];     // per-row neg bits, <<2 (idx 0,1 = padding zeros)
    __shared__ uint32_t s_nstream[8][28];  // slow path: nonzero-bit stream
    __shared__ uint32_t s_nrow[8][32];     // slow path: per-row nonzero bits

    const int lane = threadIdx.x & 31;
    const int w    = threadIdx.x >> 5;
    const int img  = blockIdx.x * 8 + w;
    if (img >= B) return;                  // warp-uniform

    const int grp = lane & 7;
    const int gsh = grp * 4;
    const bool leader = (grp == 0);

    // ---- load + binarize (neg bits via guaranteed u>>31) + zero detect ----
    const float4* xv = (const float4*)(x + (size_t)img * 784);
    float zacc = 1.0f;
    #pragma unroll
    for (int k = 0; k < 7; k++) {
        int f = k * 32 + lane;
        uint32_t val = 0;
        if (f < 196) {
            float4 v = xv[f];
            zacc = fminf(zacc, fminf(fminf(fabsf(v.x), fabsf(v.y)),
                                     fminf(fabsf(v.z), fabsf(v.w))));
            uint32_t a  = __float_as_uint(v.x), b  = __float_as_uint(v.y);
            uint32_t c2 = __float_as_uint(v.z), d2 = __float_as_uint(v.w);
            uint32_t nib = (a >> 31) | ((b >> 31) << 1) |
                           ((c2 >> 31) << 2) | ((d2 >> 31) << 3);
            val = nib << gsh;
        }
        val |= __shfl_xor_sync(0xFFFFFFFFu, val, 1);
        val |= __shfl_xor_sync(0xFFFFFFFFu, val, 2);
        val |= __shfl_xor_sync(0xFFFFFFFFu, val, 4);
        if (leader) s_stream[w][k * 4 + (lane >> 3)] = val;
    }
    __syncwarp();

    // ---- row masks: row r = stream bits [28r, 28r+28), stored <<2 ----
    if (lane < 28) {
        int bo = 28 * lane;
        uint32_t lo = s_stream[w][bo >> 5];
        uint32_t hi = s_stream[w][(bo >> 5) + 1];
        uint32_t raw = __funnelshift_r(lo, hi, bo & 31);
        s_prow[w][lane + 2] = raw << 2;
    }
    if (lane < 2) s_prow[w][lane] = 0;
    __syncwarp();

    const bool anyzero = __ballot_sync(0xFFFFFFFFu, zacc == 0.0f) != 0;

    const int p  = (lane < 25) ? lane : 24;
    const int oy = p / 5, ox = p % 5;
    const int sh6 = 6 * ox;

    uint2 cw0 = g_cw[0], cw1 = g_cw[1], cw2 = g_cw[2], cw3 = g_cw[3], cw4 = g_cw[4];

    uint32_t d0, d1, d2c, d3, d4;
    int pm;

    if (!anyzero) {
        // ================= FAST PATH (no exact-zero pixels) =================
        uint32_t xlo = 0;
        #pragma unroll
        for (int ky = 0; ky < 5; ky++) {
            uint32_t pr = s_prow[w][6 * oy + ky];
            xlo |= ((pr >> sh6) & 0x3Fu) << (6 * ky);
        }
        uint32_t xhi = (s_prow[w][6 * oy + 5] >> sh6) & 0x3Fu;

        uint32_t cm  = (ox == 0) ? 0x3Cu : 0x3Fu;
        uint32_t Mlo = cm * 0x01041041u;          // replicate over 5 ky fields
        if (oy == 0) Mlo &= 0xFFFFF000u;          // rows -2,-1 invalid
        uint32_t Mhi = cm;
        pm = ((oy == 0) ? 4 : 6) * ((ox == 0) ? 4 : 6);

        // x in NEG convention, w in POS convention: x^w = 1 <=> product +1
        d0 = __popc((xlo ^ cw0.x) & Mlo) + __popc((xhi ^ cw0.y) & Mhi);
        d1 = __popc((xlo ^ cw1.x) & Mlo) + __popc((xhi ^ cw1.y) & Mhi);
        d2c= __popc((xlo ^ cw2.x) & Mlo) + __popc((xhi ^ cw2.y) & Mhi);
        d3 = __popc((xlo ^ cw3.x) & Mlo) + __popc((xhi ^ cw3.y) & Mhi);
        d4 = __popc((xlo ^ cw4.x) & Mlo) + __popc((xhi ^ cw4.y) & Mhi);
    } else {
        // ================= SLOW PATH (rare: exact zeros present) =================
        #pragma unroll
        for (int k = 0; k < 7; k++) {
            int f = k * 32 + lane;
            uint32_t val = 0;
            if (f < 196) {
                float4 v = xv[f];
                uint32_t nn = (fabsf(v.x) > 0.f ? 1u : 0u) |
                              (fabsf(v.y) > 0.f ? 2u : 0u) |
                              (fabsf(v.z) > 0.f ? 4u : 0u) |
                              (fabsf(v.w) > 0.f ? 8u : 0u);
                val = nn << gsh;
            }
            val |= __shfl_xor_sync(0xFFFFFFFFu, val, 1);
            val |= __shfl_xor_sync(0xFFFFFFFFu, val, 2);
            val |= __shfl_xor_sync(0xFFFFFFFFu, val, 4);
            if (leader) s_nstream[w][k * 4 + (lane >> 3)] = val;
        }
        __syncwarp();
        if (lane < 28) {
            int bo = 28 * lane;
            uint32_t lo = s_nstream[w][bo >> 5];
            uint32_t hi = s_nstream[w][(bo >> 5) + 1];
            uint32_t raw = __funnelshift_r(lo, hi, bo & 31);
            s_nrow[w][lane + 2] = raw << 2;
        }
        if (lane < 2) s_nrow[w][lane] = 0;
        __syncwarp();

        pm = 0; d0 = d1 = d2c = d3 = d4 = 0;
        #pragma unroll
        for (int ky = 0; ky < 6; ky++) {
            uint32_t pr = s_prow[w][6 * oy + ky];
            uint32_t nr = s_nrow[w][6 * oy + ky];
            uint32_t xw = pr >> sh6;
            uint32_t mw = (nr >> sh6) & 0x3Fu;
            pm += __popc(mw);
            uint32_t w0 = (ky < 5) ? ((cw0.x >> (6 * ky)) & 0x3Fu) : cw0.y;
            uint32_t w1 = (ky < 5) ? ((cw1.x >> (6 * ky)) & 0x3Fu) : cw1.y;
            uint32_t w2 = (ky < 5) ? ((cw2.x >> (6 * ky)) & 0x3Fu) : cw2.y;
            uint32_t w3 = (ky < 5) ? ((cw3.x >> (6 * ky)) & 0x3Fu) : cw3.y;
            uint32_t w4 = (ky < 5) ? ((cw4.x >> (6 * ky)) & 0x3Fu) : cw4.y;
            d0 += __popc((xw ^ w0) & mw);
            d1 += __popc((xw ^ w1) & mw);
            d2c+= __popc((xw ^ w2) & mw);
            d3 += __popc((xw ^ w3) & mw);
            d4 += __popc((xw ^ w4) & mw);
        }
    }

    // ---- BN + hardtanh + sign -> ballots, fused with binary FC ----
    const bool act = (lane < 25);
    const int  j   = (lane < 10) ? lane : 0;

    uint32_t dd[5] = {d0, d1, d2c, d3, d4};
    int D = 0, pmf = 0;
    #pragma unroll
    for (int c = 0; c < 5; c++) {
        float4 bn = g_bn2[c];
        float Sf = (float)(2 * (int)dd[c] - pm);
        float y = __fadd_rn(__fmul_rn(__fsub_rn(__fadd_rn(Sf, bn.x), bn.y), bn.z), bn.w);
        uint32_t pb = __ballot_sync(0xFFFFFFFFu, act && (y > 0.f));
        uint32_t nb = __ballot_sync(0xFFFFFFFFu, act && (y < 0.f));
        uint32_t mm = pb | nb;
        pmf += __popc(mm);
        D   += __popc(~(pb ^ g_fcw[j][c]) & mm);
    }

    float4 fcc = g_fcc[j];
    float z = (float)(2 * D - pmf);
    z = __fadd_rn(z, fcc.x);
    z = __fadd_rn(__fmul_rn(__fsub_rn(z, fcc.y), fcc.z), fcc.w);

    // ---- log_softmax over 10 lanes ----
    float zv = (lane < 10) ? z : -INFINITY;
    float m = zv;
    #pragma unroll
    for (int o = 16; o; o >>= 1) m = fmaxf(m, __shfl_xor_sync(0xFFFFFFFFu, m, o));
    float e = expf(zv - m);
    float se = e;
    #pragma unroll
    for (int o = 16; o; o >>= 1) se += __shfl_xor_sync(0xFFFFFFFFu, se, o);

    if (lane < 10) out[(size_t)img * 10 + lane] = zv - m - logf(se);
}

extern "C" void kernel_launch(void* const* d_in, const int* in_sizes, int n_in,
                              void* d_out, int out_size)
{
    const float* x = (const float*)d_in[0];
    prep_kernel<<<1, 128>>>(
        (const float*)d_in[1], (const float*)d_in[2],
        (const float*)d_in[3], (const float*)d_in[4],
        (const float*)d_in[5], (const float*)d_in[6],
        (const float*)d_in[7], (const float*)d_in[8],
        (const float*)d_in[9], (const float*)d_in[10],
        (const float*)d_in[11], (const float*)d_in[12]);

    int B = in_sizes[0] / 784;
    int blocks = (B + 7) / 8;
    bnn_kernel<<<blocks, 256>>>(x, (float*)d_out, B);
}